// round 15
// baseline (speedup 1.0000x reference)
#include <cuda_runtime.h>
#include <cstdint>

#define B_ 4
#define H_ 16
#define S_ 1024
#define D_ 64
#define NTOT   ((size_t)B_ * H_ * S_ * S_)
#define NWORDS (NTOT / 32)

#define KEEP_THRESH 0xE6666600u   // bits < thresh  <=>  uniform < 0.9f (verified)

__device__ uint32_t g_mask[NWORDS];               // 8 MB dropout bitmask
// fragment-major K and V^T (bf16 hi/lo): frag = ((bh*16+kt)*4+ks)*8+n,
// 32 uint4 per frag (one per lane): {hi_w[tig], hi_w[4+tig], lo_w[tig], lo_w[4+tig]}
__device__ uint4 g_k4[B_ * H_ * S_ * D_ / 4];     // 16 MB
__device__ uint4 g_v4[B_ * H_ * S_ * D_ / 4];     // 16 MB

// ---------------------------------------------------------------------------
// Threefry-2x32, key (0,42), JAX partitionable path (bit-exact, verified)
// ---------------------------------------------------------------------------
__device__ __forceinline__ void threefry2x32(uint32_t k0, uint32_t k1,
                                             uint32_t& x0, uint32_t& x1) {
    uint32_t ks2 = 0x1BD11BDAu ^ k0 ^ k1;
    x0 += k0; x1 += k1;
#define TF_RND(r) { x0 += x1; x1 = __funnelshift_l(x1, x1, (r)); x1 ^= x0; }
    TF_RND(13) TF_RND(15) TF_RND(26) TF_RND(6)
    x0 += k1;  x1 += ks2 + 1u;
    TF_RND(17) TF_RND(29) TF_RND(16) TF_RND(24)
    x0 += ks2; x1 += k0 + 2u;
    TF_RND(13) TF_RND(15) TF_RND(26) TF_RND(6)
    x0 += k0;  x1 += k1 + 3u;
    TF_RND(17) TF_RND(29) TF_RND(16) TF_RND(24)
    x0 += k1;  x1 += ks2 + 4u;
    TF_RND(13) TF_RND(15) TF_RND(26) TF_RND(6)
    x0 += ks2; x1 += k0 + 5u;
#undef TF_RND
}

// ---------------------------------------------------------------------------
// bf16 helpers
// ---------------------------------------------------------------------------
__device__ __forceinline__ uint32_t pack2(float lo, float hi) {
    uint32_t r;
    asm("cvt.rn.bf16x2.f32 %0, %1, %2;" : "=r"(r) : "f"(hi), "f"(lo));
    return r;
}
__device__ __forceinline__ float blo(uint32_t w) { return __uint_as_float(w << 16); }
__device__ __forceinline__ float bhi(uint32_t w) { return __uint_as_float(w & 0xffff0000u); }
__device__ __forceinline__ void split2(float a, float b, uint32_t& h, uint32_t& l) {
    h = pack2(a, b);
    l = pack2(a - blo(h), b - bhi(h));
}

// ---------------------------------------------------------------------------
// Kernel 1: mask (blocks 0..8191) + K frag-convert (8192..9215)
//           + V frag-convert/transpose (9216..10239)
// ---------------------------------------------------------------------------
#define MASK_BLKS 8192
#define KC_BLKS   1024
#define VSTR      65

__global__ void __launch_bounds__(256) prep_kernel(const float* __restrict__ K,
                                                   const float* __restrict__ V) {
    __shared__ float vsm[64 * VSTR];
    const int b = blockIdx.x;
    const int tid = threadIdx.x;

    if (b < MASK_BLKS) {
        uint32_t base = (uint32_t)(b * 256 + tid) * 32u;
        uint32_t w = 0u;
#pragma unroll 4
        for (int i = 0; i < 32; i++) {
            uint32_t x0 = 0u, x1 = base + (uint32_t)i;
            threefry2x32(0u, 42u, x0, x1);
            w |= (((x0 ^ x1) < KEEP_THRESH) ? 1u : 0u) << i;
        }
        g_mask[b * 256 + tid] = w;
    } else if (b < MASK_BLKS + KC_BLKS) {
        // ---- K: row grow, quarter q=ks; write fragment-major ----
        int grow = (b - MASK_BLKS) * 64 + (tid >> 2);   // global key row
        int q = tid & 3;                                 // ks
        const float4* src = reinterpret_cast<const float4*>(K + grow * 64 + q * 16);
        uint32_t hw[8], lw[8];
#pragma unroll
        for (int i = 0; i < 4; i++) {
            float4 v = src[i];
            split2(v.x, v.y, hw[2 * i],     lw[2 * i]);
            split2(v.z, v.w, hw[2 * i + 1], lw[2 * i + 1]);
        }
        int n = (grow >> 3) & 7, gid = grow & 7;
        int ktbh = grow >> 6;                            // bh*16 + kt
        uint4* dst = g_k4 + ((size_t)((ktbh * 4 + q) * 8 + n)) * 32 + gid * 4;
        dst[0] = make_uint4(hw[0], hw[4], lw[0], lw[4]);
        dst[1] = make_uint4(hw[1], hw[5], lw[1], lw[5]);
        dst[2] = make_uint4(hw[2], hw[6], lw[2], lw[6]);
        dst[3] = make_uint4(hw[3], hw[7], lw[3], lw[7]);
    } else {
        // ---- V: transpose tile, write fragment-major ----
        int bb = b - MASK_BLKS - KC_BLKS;               // bh*16 + kt
        const float* Vt = V + (size_t)bb * 64 * 64;
#pragma unroll
        for (int i = 0; i < 4; i++) {
            int lin = tid + (i << 8);
            int row = lin >> 4, qd = (lin & 15) << 2;
            float4 v = *reinterpret_cast<const float4*>(Vt + row * 64 + qd);
            float* d = vsm + row * VSTR + qd;
            d[0] = v.x; d[1] = v.y; d[2] = v.z; d[3] = v.w;
        }
        __syncthreads();
        int od = tid >> 2;                              // d row 0..63
        int kq = tid & 3;                               // ks
        uint32_t hw[8], lw[8];
#pragma unroll
        for (int j = 0; j < 8; j++) {
            int kp = kq * 8 + j;
            float f0 = vsm[(2 * kp) * VSTR + od];
            float f1 = vsm[(2 * kp + 1) * VSTR + od];
            split2(f0, f1, hw[j], lw[j]);
        }
        uint4* dst = g_v4 + ((size_t)((bb * 4 + kq) * 8 + (od >> 3))) * 32
                     + (od & 7) * 4;
        dst[0] = make_uint4(hw[0], hw[4], lw[0], lw[4]);
        dst[1] = make_uint4(hw[1], hw[5], lw[1], lw[5]);
        dst[2] = make_uint4(hw[2], hw[6], lw[2], lw[6]);
        dst[3] = make_uint4(hw[3], hw[7], lw[3], lw[7]);
    }
}

// ---------------------------------------------------------------------------
// Attention: barrier-free mainloop; K/V fragments via coalesced LDG.128
// ---------------------------------------------------------------------------
__device__ __forceinline__ void mma16(float d[4], const uint32_t a[4],
                                      uint32_t b0, uint32_t b1) {
    asm volatile(
        "mma.sync.aligned.m16n8k16.row.col.f32.bf16.bf16.f32 "
        "{%0,%1,%2,%3}, {%4,%5,%6,%7}, {%8,%9}, {%0,%1,%2,%3};"
        : "+f"(d[0]), "+f"(d[1]), "+f"(d[2]), "+f"(d[3])
        : "r"(a[0]), "r"(a[1]), "r"(a[2]), "r"(a[3]), "r"(b0), "r"(b1));
}
__device__ __forceinline__ void ldm_x4(uint32_t r[4], uint32_t addr) {
    asm volatile("ldmatrix.sync.aligned.m8n8.x4.shared.b16 {%0,%1,%2,%3}, [%4];"
                 : "=r"(r[0]), "=r"(r[1]), "=r"(r[2]), "=r"(r[3]) : "r"(addr));
}

#define PW 36   // bf16x2 word stride for Q smem (conflict-free ldmatrix)
#define W_QH 0
#define W_QL (128 * PW)
#define W_TOT (2 * 128 * PW)             // 9216 words = 36864 B

__global__ void __launch_bounds__(256, 2)
attn_kernel(const float* __restrict__ Q, const uint32_t* __restrict__ scale_ptr,
            float* __restrict__ O) {
    extern __shared__ uint32_t smw[];

    const int tid  = threadIdx.x;
    const int warp = tid >> 5;
    const int lane = tid & 31;
    const int gid  = lane >> 2;
    const int tig  = lane & 3;
    const int bh   = blockIdx.y;
    const int qb   = blockIdx.x << 7;
    const int r0   = warp * 16 + gid;

    uint32_t sw = *scale_ptr;
    float scale = (sw & 0x7f800000u) ? __uint_as_float(sw) : (float)(int)sw;

    const uint32_t sb = (uint32_t)__cvta_generic_to_shared(smw);
    const uint32_t laneA = (uint32_t)((lane & 15) * PW + ((lane & 16) ? 4 : 0));
    const uint32_t aQH = sb + 4u * (W_QH + (uint32_t)(warp * 16) * PW + laneA);
    const uint32_t aQL = sb + 4u * (W_QL + (uint32_t)(warp * 16) * PW + laneA);

    // per-lane fragment pointers (uint4 units): bh base + lane
    const uint4* Kf = g_k4 + (size_t)bh * 16384 + lane;
    const uint4* Vf = g_v4 + (size_t)bh * 16384 + lane;

    // ---- Q prologue: stage scaled hi/lo bf16x2 words into smem ----
    {
        int r = tid >> 1, half = (tid & 1) * 32;
        const float4* Qp = reinterpret_cast<const float4*>(
            Q + ((size_t)bh * S_ + qb + r) * D_ + half);
        int wb = r * PW + (half >> 1);
#pragma unroll
        for (int i = 0; i < 8; i++) {
            float4 v = Qp[i];
            uint32_t h0, l0, h1, l1;
            split2(v.x * scale, v.y * scale, h0, l0);
            split2(v.z * scale, v.w * scale, h1, l1);
            smw[W_QH + wb + 2 * i]     = h0;
            smw[W_QH + wb + 2 * i + 1] = h1;
            smw[W_QL + wb + 2 * i]     = l0;
            smw[W_QL + wb + 2 * i + 1] = l1;
        }
    }

    float m_[2], l_[2];
    float o[8][4];
    m_[0] = m_[1] = -1e30f;
    l_[0] = l_[1] = 0.f;
#pragma unroll
    for (int n = 0; n < 8; n++)
#pragma unroll
        for (int c = 0; c < 4; c++) o[n][c] = 0.f;

    __syncthreads();                     // Q visible; ONLY barrier in kernel

#pragma unroll 1
    for (int t = 0; t < 16; t++) {
        // ---- mask prefetch (hidden under QK) ----
        uint2 mw[2];
#pragma unroll
        for (int h = 0; h < 2; h++) {
            size_t rg = (size_t)(bh * S_ + qb + r0 + 8 * h);
            mw[h] = *reinterpret_cast<const uint2*>(g_mask + (rg << 5) + t * 2);
        }

        const uint4* Kt4 = Kf + (size_t)t * 1024;   // tile base (uint4)
        const uint4* Vt4 = Vf + (size_t)t * 1024;

        // ---- QK: 3-term bf16, K frags via coalesced LDG.128 ----
        float s[8][4];
#pragma unroll
        for (int n = 0; n < 8; n++)
#pragma unroll
            for (int c = 0; c < 4; c++) s[n][c] = 0.f;

#pragma unroll
        for (int ks = 0; ks < 4; ks++) {
            uint32_t qh[4], ql[4];
            ldm_x4(qh, aQH + ks * 32u);
            ldm_x4(ql, aQL + ks * 32u);
#pragma unroll
            for (int n = 0; n < 8; n++) {
                uint4 kb = Kt4[(ks * 8 + n) * 32];
                mma16(s[n], qh, kb.x, kb.y);
                mma16(s[n], ql, kb.x, kb.y);
                mma16(s[n], qh, kb.z, kb.w);
            }
        }

        // ---- online softmax (rows on lane quads; warps free-running) ----
#pragma unroll
        for (int h = 0; h < 2; h++) {
            float mx = -1e30f;
#pragma unroll
            for (int n = 0; n < 8; n++)
                mx = fmaxf(mx, fmaxf(s[n][2 * h], s[n][2 * h + 1]));
            mx = fmaxf(mx, __shfl_xor_sync(0xffffffffu, mx, 1));
            mx = fmaxf(mx, __shfl_xor_sync(0xffffffffu, mx, 2));
            float mnew = fmaxf(m_[h], mx);
            float corr = __expf(m_[h] - mnew);
            m_[h] = mnew;
            float sum = 0.f;
#pragma unroll
            for (int n = 0; n < 8; n++) {
                float e0 = __expf(s[n][2 * h] - mnew);
                float e1 = __expf(s[n][2 * h + 1] - mnew);
                s[n][2 * h] = e0;
                s[n][2 * h + 1] = e1;
                sum += e0 + e1;
            }
            sum += __shfl_xor_sync(0xffffffffu, sum, 1);
            sum += __shfl_xor_sync(0xffffffffu, sum, 2);
            l_[h] = l_[h] * corr + sum;
#pragma unroll
            for (int n = 0; n < 8; n++) {
                o[n][2 * h] *= corr;
                o[n][2 * h + 1] *= corr;
            }
        }

        // ---- PV: dropout + pack P in regs; V frags via LDG.128 ----
#pragma unroll
        for (int ks = 0; ks < 4; ks++) {
            uint32_t aph[4], apl[4];
#pragma unroll
            for (int q = 0; q < 4; q++) {
                int n = 2 * ks + (q >> 1);
                int h = q & 1;
                uint32_t word = (n < 4) ? mw[h].x : mw[h].y;
                int bit0 = (n & 3) * 8 + 2 * tig;
                float p0 = ((word >> bit0) & 1u) ? s[n][2 * h] : 0.f;
                float p1 = ((word >> (bit0 + 1)) & 1u) ? s[n][2 * h + 1] : 0.f;
                int ar = (q >> 1) * 2 + h;
                split2(p0, p1, aph[ar], apl[ar]);
            }
#pragma unroll
            for (int n = 0; n < 8; n++) {
                uint4 vb = Vt4[(ks * 8 + n) * 32];
                mma16(o[n], aph, vb.x, vb.y);
                mma16(o[n], aph, vb.z, vb.w);
                mma16(o[n], apl, vb.x, vb.y);
            }
        }
    }

    // ---- epilogue: O / (0.9 * l) ----
#pragma unroll
    for (int h = 0; h < 2; h++) {
        float inv = 1.f / (0.9f * l_[h]);
        int row = qb + r0 + h * 8;
        float* Op = O + ((size_t)bh * S_ + row) * D_;
#pragma unroll
        for (int n = 0; n < 8; n++) {
            float2 v;
            v.x = o[n][2 * h] * inv;
            v.y = o[n][2 * h + 1] * inv;
            *reinterpret_cast<float2*>(Op + n * 8 + 2 * tig) = v;
        }
    }
}

// ---------------------------------------------------------------------------
extern "C" void kernel_launch(void* const* d_in, const int* in_sizes, int n_in,
                              void* d_out, int out_size) {
    (void)in_sizes; (void)n_in; (void)out_size;
    const float*    Q  = (const float*)d_in[0];
    const float*    K  = (const float*)d_in[1];
    const float*    V  = (const float*)d_in[2];
    const uint32_t* SC = (const uint32_t*)d_in[3];
    float*          O  = (float*)d_out;

    prep_kernel<<<MASK_BLKS + 2 * KC_BLKS, 256>>>(K, V);

    const int smem = W_TOT * (int)sizeof(uint32_t);   // 36864 B
    cudaFuncSetAttribute(attn_kernel,
                         cudaFuncAttributeMaxDynamicSharedMemorySize, smem);
    dim3 grid(S_ / 128, B_ * H_);
    attn_kernel<<<grid, 256, smem>>>(Q, SC, O);
}